// round 11
// baseline (speedup 1.0000x reference)
#include <cuda_runtime.h>
#include <cuda_bf16.h>

#define N_TOTAL 8700
#define N_YOLO  8400
#define N_WORDS 136          // ceil(8700/64)
#define N_PAD   8704
#define LAST_BITS 60         // 8700 - 135*64
#define CAP     8192         // per-column sparse entry capacity
#define MPT     4            // scan: register entries per thread (256*4 = 1024/column)
#define PCAP    131072       // pair list capacity (~10x expected)
#define TPB     512
#define RBLK    272          // rank blocks (32 rows each)
#define IGW     9            // iou word-groups (16 words each, covers 144 >= 136)
#define IBLK    (136 * IGW)  // 1224 iou tiles
#define GRID    (RBLK + IBLK)

// ---------------- scratch (static device globals; zero-init; leave-clean protocol) ----------
__device__ float s_x1[N_PAD], s_y1[N_PAD], s_x2[N_PAD], s_y2[N_PAD], s_conf[N_PAD];
__device__ int g_rank_orig[N_PAD];
__device__ int g_npairs;                               // reset by k_scanout
__device__ uint2 g_pairs[PCAP];
__device__ int col_count[N_WORDS];                     // reset by k_scanout
__device__ ulonglong2 col_ent[N_WORDS][CAP];           // .x = row i (sorted), .y = bit word
__device__ unsigned long long g_diag[N_PAD];           // reset by k_scanout
__device__ unsigned long long g_hasdiag[N_WORDS];      // reset by k_scanout

// key: descending clipped conf, ties -> ascending original concat index (stable argsort)
__device__ __forceinline__ unsigned long long make_key(
    int j, const float* __restrict__ yc, const float* __restrict__ rc) {
    if (j >= N_TOTAL) return 0ull;
    float c = (j < N_YOLO) ? yc[j] : rc[j - N_YOLO];
    c = fminf(fmaxf(c, 0.0f), 1.0f);
    return ((unsigned long long)__float_as_uint(c) << 32)
         | (unsigned long long)(0xFFFFFFFFu - (unsigned)j);
}

// xyxy from raw inputs — op sequence identical everywhere (bit-exact)
__device__ __forceinline__ void make_box(
    int j, const float* __restrict__ yb, const float* __restrict__ rb,
    float& x1, float& y1, float& x2, float& y2) {
    if (j >= N_TOTAL) { x1 = y1 = x2 = y2 = 0.0f; return; }
    float4 p = (j < N_YOLO) ? *(const float4*)(yb + 4 * j)
                            : *(const float4*)(rb + 4 * (j - N_YOLO));
    float hw = __fmul_rn(p.z, 0.5f);
    float hh = __fmul_rn(p.w, 0.5f);
    x1 = __fsub_rn(p.x, hw); y1 = __fsub_rn(p.y, hh);
    x2 = __fadd_rn(p.x, hw); y2 = __fadd_rn(p.y, hh);
}

// ---------------- Node 1: rank+scatter blocks || iou-pair blocks (co-scheduled) ----------
__global__ void __launch_bounds__(TPB) k_main(
        const float* __restrict__ yb, const float* __restrict__ yc,
        const float* __restrict__ rb, const float* __restrict__ rc) {
    __shared__ __align__(16) char smem_u[21504];
    const int tid = threadIdx.x;
    const int bid = blockIdx.x;

    if (bid < RBLK) {
        // ======== rank + scatter: block owns rows [bid*32, bid*32+32) ========
        unsigned long long* skey = (unsigned long long*)smem_u;      // 17408 B
        int (*scnt)[32] = (int(*)[32])(smem_u + 17408);              //  2048 B
        const int il = tid & 31;
        const int stripe = tid >> 5;                   // 0..15
        const int i = bid * 32 + il;
        const unsigned long long ki = make_key(i, yc, rc);
        int cnt = 0;
        for (int base = 0; base < N_PAD; base += 2176) {
            for (int t = tid; t < 2176; t += TPB)
                skey[t] = make_key(base + t, yc, rc);
            __syncthreads();
            const int lo = stripe * 136;
#pragma unroll 8
            for (int t = 0; t < 136; t++)
                cnt += (skey[lo + t] > ki) ? 1 : 0;
            __syncthreads();
        }
        scnt[stripe][il] = cnt;
        __syncthreads();
        if (tid < 32) {
            int r = 0;
#pragma unroll
            for (int s2 = 0; s2 < 16; s2++) r += scnt[s2][tid];
            const int ii = bid * 32 + tid;
            g_rank_orig[ii] = r;
            float ox1, oy1, ox2, oy2;
            make_box(ii, yb, rb, ox1, oy1, ox2, oy2);
            float oc = 0.0f;
            if (ii < N_TOTAL) {
                float c = (ii < N_YOLO) ? yc[ii] : rc[ii - N_YOLO];
                oc = fminf(fmaxf(c, 0.0f), 1.0f);
            }
            s_x1[r] = ox1; s_y1[r] = oy1;
            s_x2[r] = ox2; s_y2[r] = oy2;
            s_conf[r] = oc;
        }
    } else {
        // ======== iou pairs on UNSORTED boxes: tile = 64 a's x 1024 j's ========
        float4* jb = (float4*)smem_u;                  // 16384 B
        float*  ja = (float*)(smem_u + 16384);         //  4096 B
        const int t = bid - RBLK;
        const int ig = t / IGW;                        // a-range [ig*64, ig*64+64)
        const int wg = t % IGW;                        // j-range [wg*1024, +1024)
        const int i0 = ig * 64;
        const int jb0 = wg * 1024;
        if (jb0 + 1024 <= i0) return;                  // all j <= a: nothing to emit
        for (int tt = tid; tt < 1024; tt += TPB) {
            int j = jb0 + tt;
            float x1, y1, x2, y2;
            make_box(j, yb, rb, x1, y1, x2, y2);       // pads/beyond -> zero box
            jb[tt] = make_float4(x1, y1, x2, y2);
            ja[tt] = __fmul_rn(__fsub_rn(x2, x1), __fsub_rn(y2, y1));
        }
        __syncthreads();
        const int il = tid & 31;
        const int wl = tid >> 5;                       // 0..15
        const int word = wg * 16 + wl;
        if (word >= N_WORDS) return;
        const int jbase = word * 64;
        if (jbase + 64 <= i0) return;                  // whole word below a-range
        const int a1 = i0 + il;                        // <= 8671, real
        const int a2 = a1 + 32;                        // may be pad (zero box: no hits)
        float ax1, ay1, ax2, ay2, bx1, by1, bx2, by2;
        make_box(a1, yb, rb, ax1, ay1, ax2, ay2);
        make_box(a2, yb, rb, bx1, by1, bx2, by2);
        float aa = __fmul_rn(__fsub_rn(ax2, ax1), __fsub_rn(ay2, ay1));
        float ab = __fmul_rn(__fsub_rn(bx2, bx1), __fsub_rn(by2, by1));
        const int tb = wl * 64;
#pragma unroll 8
        for (int b = 0; b < 64; b++) {
            float4 J = jb[tb + b];
            float aj = ja[tb + b];
            int j = jbase + b;
            float iw1 = fmaxf(__fsub_rn(fminf(ax2, J.z), fmaxf(ax1, J.x)), 0.0f);
            float ih1 = fmaxf(__fsub_rn(fminf(ay2, J.w), fmaxf(ay1, J.y)), 0.0f);
            float in1 = __fmul_rn(iw1, ih1);
            float un1 = __fsub_rn(__fadd_rn(aa, aj), in1);
            if (in1 > __fmul_rn(0.49f, un1)) {         // safe pre-filter
                if (__fdiv_rn(in1, fmaxf(un1, 1e-9f)) > 0.5f && j > a1) {
                    int pos = atomicAdd(&g_npairs, 1);
                    if (pos < PCAP) g_pairs[pos] = make_uint2((unsigned)a1, (unsigned)j);
                }
            }
            float iw2 = fmaxf(__fsub_rn(fminf(bx2, J.z), fmaxf(bx1, J.x)), 0.0f);
            float ih2 = fmaxf(__fsub_rn(fminf(by2, J.w), fmaxf(by1, J.y)), 0.0f);
            float in2 = __fmul_rn(iw2, ih2);
            float un2 = __fsub_rn(__fadd_rn(ab, aj), in2);
            if (in2 > __fmul_rn(0.49f, un2)) {
                if (__fdiv_rn(in2, fmaxf(un2, 1e-9f)) > 0.5f && j > a2) {
                    int pos = atomicAdd(&g_npairs, 1);
                    if (pos < PCAP) g_pairs[pos] = make_uint2((unsigned)a2, (unsigned)j);
                }
            }
        }
    }
}

// ---------------- Node 2: remap pairs into sorted space ----------------
__global__ void k_remap() {
    int n = g_npairs;
    if (n > PCAP) n = PCAP;
    for (int k = blockIdx.x * blockDim.x + threadIdx.x; k < n;
         k += gridDim.x * blockDim.x) {
        uint2 p = g_pairs[k];
        int ra = g_rank_orig[p.x];
        int rb = g_rank_orig[p.y];
        int i = min(ra, rb);
        int j = max(ra, rb);
        int w = j >> 6;
        unsigned long long bit = 1ull << (j & 63);
        if (w == (i >> 6)) {
            atomicOr(&g_diag[i], bit);
            atomicOr(&g_hasdiag[w], 1ull << (i & 63));
        } else {
            int pos = atomicAdd(&col_count[w], 1);
            if (pos < CAP)
                col_ent[w][pos] = make_ulonglong2((unsigned long long)i, bit);
        }
    }
}

// ---------------- Node 3: 8-warp scan + fused output + leave-clean reset ----------------
__global__ void k_scanout(float* __restrict__ out) {
    __shared__ unsigned long long kw[N_WORDS];
    __shared__ unsigned long long hds[N_WORDS];
    __shared__ unsigned long long remv_out[N_WORDS];
    __shared__ int scol[N_WORDS];
    __shared__ unsigned long long s_part[8];
    const int tid = threadIdx.x;
    const int wid = tid >> 5, lane = tid & 31;
    if (tid < N_WORDS) {
        hds[tid] = g_hasdiag[tid];
        int c = col_count[tid];
        scol[tid] = (c > CAP) ? CAP : c;
    }
    __syncthreads();

    ulonglong2 eA[MPT], eB[MPT];
    {
        int cA = scol[0];
#pragma unroll
        for (int m = 0; m < MPT; m++) {
            int k = tid + (m << 8);
            eA[m] = (k < cA) ? col_ent[0][k] : make_ulonglong2(0ull, 0ull);
        }
        int cB = scol[1];
#pragma unroll
        for (int m = 0; m < MPT; m++) {
            int k = tid + (m << 8);
            eB[m] = (k < cB) ? col_ent[1][k] : make_ulonglong2(0ull, 0ull);
        }
    }

    for (int g = 0; g < N_WORDS; g++) {
        unsigned long long valid = (g == N_WORDS - 1) ? ((1ull << LAST_BITS) - 1ull)
                                                      : ~0ull;
        unsigned long long pre_d0 = 0, pre_d1 = 0, pre_d2 = 0, pre_d3 = 0;
        int pre_b0 = -1, pre_b1 = -1, pre_b2 = -1, pre_b3 = -1;
        unsigned long long hd = 0ull;
        if (tid == 0) {
            hd = hds[g] & valid;
            unsigned long long t = hd;
            if (t) { pre_b0 = __ffsll(t) - 1; t &= t - 1; pre_d0 = g_diag[g * 64 + pre_b0]; }
            if (t) { pre_b1 = __ffsll(t) - 1; t &= t - 1; pre_d1 = g_diag[g * 64 + pre_b1]; }
            if (t) { pre_b2 = __ffsll(t) - 1; t &= t - 1; pre_d2 = g_diag[g * 64 + pre_b2]; }
            if (t) { pre_b3 = __ffsll(t) - 1;             pre_d3 = g_diag[g * 64 + pre_b3]; }
        }
        int cnt = scol[g];
        unsigned long long part = 0ull;
        if (g & 1) {
#pragma unroll
            for (int m = 0; m < MPT; m++) {
                int i = (int)eB[m].x;
                if ((kw[i >> 6] >> (i & 63)) & 1ull) part |= eB[m].y;
            }
        } else {
#pragma unroll
            for (int m = 0; m < MPT; m++) {
                int i = (int)eA[m].x;
                if ((kw[i >> 6] >> (i & 63)) & 1ull) part |= eA[m].y;
            }
        }
        for (int k = (MPT << 8) + tid; k < cnt; k += 256) {
            ulonglong2 e = col_ent[g][k];
            int i = (int)e.x;
            if ((kw[i >> 6] >> (i & 63)) & 1ull) part |= e.y;
        }
        unsigned lo = __reduce_or_sync(0xFFFFFFFFu, (unsigned)part);
        unsigned hi = __reduce_or_sync(0xFFFFFFFFu, (unsigned)(part >> 32));
        if (lane == 0) s_part[wid] = ((unsigned long long)hi << 32) | lo;
        int g2 = g + 2;
        if (g2 < N_WORDS) {
            int c2 = scol[g2];
            if (g & 1) {
#pragma unroll
                for (int m = 0; m < MPT; m++) {
                    int k = tid + (m << 8);
                    eB[m] = (k < c2) ? col_ent[g2][k] : make_ulonglong2(0ull, 0ull);
                }
            } else {
#pragma unroll
                for (int m = 0; m < MPT; m++) {
                    int k = tid + (m << 8);
                    eA[m] = (k < c2) ? col_ent[g2][k] : make_ulonglong2(0ull, 0ull);
                }
            }
        }
        __syncthreads();
        if (tid == 0) {
            unsigned long long removed = 0ull;
#pragma unroll
            for (int w = 0; w < 8; w++) removed |= s_part[w];
            unsigned long long m = hd & ~removed;
            while (m) {
                int b = __ffsll(m) - 1;
                if (!((removed >> b) & 1ull)) {
                    unsigned long long d;
                    if      (b == pre_b0) d = pre_d0;
                    else if (b == pre_b1) d = pre_d1;
                    else if (b == pre_b2) d = pre_d2;
                    else if (b == pre_b3) d = pre_d3;
                    else                  d = g_diag[g * 64 + b];
                    removed |= d;
                }
                m &= m - 1;
                m &= ~removed;
            }
            kw[g] = valid & ~removed;
            remv_out[g] = removed;
        }
        __syncthreads();
    }

    // fused output
    for (int r = tid; r < N_TOTAL; r += 256) {
        bool keep = !((remv_out[r >> 6] >> (r & 63)) & 1ull);
        float m = keep ? 1.0f : 0.0f;
        out[r * 5 + 0] = __fmul_rn(s_x1[r], m);
        out[r * 5 + 1] = __fmul_rn(s_y1[r], m);
        out[r * 5 + 2] = __fmul_rn(s_x2[r], m);
        out[r * 5 + 3] = __fmul_rn(s_y2[r], m);
        out[r * 5 + 4] = __fmul_rn(s_conf[r], m);
    }

    // leave-clean: reset sparse state for the next invocation (all scan reads are done)
    if (tid == 0) g_npairs = 0;
    if (tid < N_WORDS) { col_count[tid] = 0; g_hasdiag[tid] = 0ull; }
    for (int r = tid; r < N_PAD; r += 256) g_diag[r] = 0ull;
}

// ---------------- launch ----------------
extern "C" void kernel_launch(void* const* d_in, const int* in_sizes, int n_in,
                              void* d_out, int out_size) {
    const float* yb = (const float*)d_in[0];   // yolo_cxcywh   [8400,4]
    const float* yc = (const float*)d_in[1];   // yolo_conf     [8400]
    const float* rb = (const float*)d_in[2];   // rtdetr_cxcywh [300,4]
    const float* rc = (const float*)d_in[3];   // rtdetr_conf   [300]
    float* out = (float*)d_out;

    k_main<<<GRID, TPB>>>(yb, yc, rb, rc);     // rank blocks + iou blocks co-scheduled
    k_remap<<<96, 256>>>();
    k_scanout<<<1, 256>>>(out);
}